// round 5
// baseline (speedup 1.0000x reference)
#include <cuda_runtime.h>
#include <cuda_bf16.h>
#include <cstdint>

// Problem constants
#define BB 2
#define HH 16
#define TT 8192
#define DD 64
#define MM 8
#define PP 32                 // DD/2 rotation pairs
#define NVEC (BB*HH*TT)       // 262144 vectors per tensor
#define VPB 128               // vectors per block
#define BLOCKS_PER_TENSOR (NVEC / VPB)   // 2048
#define TILE_BYTES (VPB * DD * 4)        // 32768

// WY representation of the composed reflections (per head):
//   H0*H1*...*H7 = I + W * Y^T,  W columns = [u7, u6, ..., u0]
__device__ float g_Wt[HH*MM*DD];   // [h][j][i]
__device__ float g_Yt[HH*MM*DD];   // [h][j][i]

__device__ __forceinline__ uint32_t smem_u32(const void* p) {
    uint32_t a;
    asm("{ .reg .u64 t; cvta.to.shared.u64 t, %1; cvt.u32.u64 %0, t; }"
        : "=r"(a) : "l"(p));
    return a;
}

// ---------------------------------------------------------------------------
// Prep: normalize V -> u_m, build WY form. One warp per head.
// ---------------------------------------------------------------------------
__global__ void prep_wy_kernel(const float* __restrict__ V) {
    int h = blockIdx.x;
    int lane = threadIdx.x;

    float u0[MM], u1[MM];
    #pragma unroll
    for (int m = 0; m < MM; m++) {
        float a = V[(h*MM + m)*DD + lane];
        float b = V[(h*MM + m)*DD + 32 + lane];
        float ss = a*a + b*b;
        #pragma unroll
        for (int o = 16; o > 0; o >>= 1) ss += __shfl_xor_sync(0xffffffffu, ss, o);
        float inv = 1.0f / sqrtf(ss + 1e-16f);   // EPS=1e-8 -> EPS^2
        u0[m] = a * inv;
        u1[m] = b * inv;
    }

    float y0[MM], y1[MM];
    y0[0] = -2.0f * u0[7];
    y1[0] = -2.0f * u1[7];
    #pragma unroll
    for (int j = 1; j < MM; j++) {
        float a = u0[7-j], b = u1[7-j];
        float acc0 = -2.0f * a;
        float acc1 = -2.0f * b;
        #pragma unroll
        for (int c = 0; c < MM; c++) {
            if (c < j) {
                float d = u0[7-c]*a + u1[7-c]*b;
                #pragma unroll
                for (int o = 16; o > 0; o >>= 1) d += __shfl_xor_sync(0xffffffffu, d, o);
                float s = -2.0f * d;
                acc0 = fmaf(s, y0[c], acc0);
                acc1 = fmaf(s, y1[c], acc1);
            }
        }
        y0[j] = acc0;
        y1[j] = acc1;
    }

    #pragma unroll
    for (int j = 0; j < MM; j++) {
        g_Wt[(h*MM + j)*DD + lane]      = u0[7-j];
        g_Wt[(h*MM + j)*DD + 32 + lane] = u1[7-j];
        g_Yt[(h*MM + j)*DD + lane]      = y0[j];
        g_Yt[(h*MM + j)*DD + 32 + lane] = y1[j];
    }
}

// Range reduction: 2*pi = RC1 + RC2 + RC3 (RC1/RC2 short mantissas)
#define INV2PI 0.15915494309189535f
#define RC1 6.283203125f
#define RC2 (-1.78217887878418e-5f)
#define RC3 3.9683738e-9f

// ---------------------------------------------------------------------------
// Main kernel. Bulk-async in -> rotated-column compute -> bulk-async out.
// Thread t owns vector t of the tile; accesses its 16 float4 columns in
// order (t+s)&15 so every 8-lane LDS/STS phase is bank-conflict-free.
// ---------------------------------------------------------------------------
__global__ void __launch_bounds__(128, 4)
hh_rope_kernel(const float* __restrict__ q,
               const float* __restrict__ k,
               const float* __restrict__ pos,
               const float* __restrict__ freq,
               float* __restrict__ out) {
    __shared__ __align__(128) float sBuf[VPB * DD];   // 32 KB, linear
    __shared__ __align__(16)  float sY[MM * DD];      // 2 KB
    __shared__ __align__(16)  float sW[MM * DD];      // 2 KB
    __shared__ float sFreq[PP];
    __shared__ __align__(8) unsigned long long sMbar;

    int tid = threadIdx.x;
    int bid = blockIdx.x;
    int tensor = bid >> 11;                 // 2048 blocks per tensor
    int vloc = (bid & 2047) * VPB;
    int h = (vloc >> 13) & (HH - 1);
    int t0 = vloc & (TT - 1);

    uint32_t mbar = smem_u32(&sMbar);
    uint32_t bufA = smem_u32(sBuf);

    if (tid == 0) {
        asm volatile("mbarrier.init.shared.b64 [%0], 1;" :: "r"(mbar) : "memory");
        asm volatile("fence.proxy.async.shared::cta;" ::: "memory");
    }
    __syncthreads();

    if (tid == 0) {
        asm volatile("mbarrier.arrive.expect_tx.shared.b64 _, [%0], %1;"
                     :: "r"(mbar), "r"((uint32_t)TILE_BYTES) : "memory");
        const float* src = (tensor ? k : q) + (size_t)vloc * DD;
        asm volatile("cp.async.bulk.shared::cta.global.mbarrier::complete_tx::bytes "
                     "[%0], [%1], %2, [%3];"
                     :: "r"(bufA), "l"(src), "r"((uint32_t)TILE_BYTES), "r"(mbar)
                     : "memory");
    }

    // Overlap with the bulk load: stage W/Y/freq, read pos
    {
        const float4* gY4 = (const float4*)(g_Yt + h*MM*DD);
        const float4* gW4 = (const float4*)(g_Wt + h*MM*DD);
        ((float4*)sY)[tid] = gY4[tid];
        ((float4*)sW)[tid] = gW4[tid];
        if (tid < PP) sFreq[tid] = freq[tid];
    }
    float tf = pos[t0 + tid];
    __syncthreads();

    // Wait for the tile
    {
        uint32_t done;
        asm volatile(
            "{\n\t"
            ".reg .pred p;\n\t"
            "mbarrier.try_wait.parity.shared.b64 p, [%1], 0;\n\t"
            "selp.b32 %0, 1, 0, p;\n\t"
            "}" : "=r"(done) : "r"(mbar) : "memory");
        if (!done) {
            asm volatile(
                "{\n\t"
                ".reg .pred P1;\n\t"
                "W0_%=:\n\t"
                "mbarrier.try_wait.parity.shared.b64 P1, [%0], 0, 0x989680;\n\t"
                "@P1 bra.uni W1_%=;\n\t"
                "bra.uni W0_%=;\n\t"
                "W1_%=:\n\t"
                "}" :: "r"(mbar) : "memory");
        }
    }

    // Gather own vector (rotated columns, conflict-free)
    const char* myRow = (const char*)sBuf + tid * (DD * 4);
    float4 z[16];
    #pragma unroll
    for (int s = 0; s < 16; s++) {
        int col = (tid + s) & 15;
        z[s] = *(const float4*)(myRow + col * 16);
    }

    // Stage 1: c_j = Y_j . z  (8 independent dots; per-thread column order rotated)
    float c[MM];
    #pragma unroll
    for (int j = 0; j < MM; j++) {
        const char* yrow = (const char*)sY + j * (DD * 4);
        float a0 = 0.f, a1 = 0.f, a2 = 0.f, a3 = 0.f;
        #pragma unroll
        for (int s = 0; s < 16; s += 4) {
            float4 y0 = *(const float4*)(yrow + (((tid + s    ) & 15) * 16));
            float4 y1 = *(const float4*)(yrow + (((tid + s + 1) & 15) * 16));
            float4 y2 = *(const float4*)(yrow + (((tid + s + 2) & 15) * 16));
            float4 y3 = *(const float4*)(yrow + (((tid + s + 3) & 15) * 16));
            a0 = fmaf(z[s  ].x,y0.x, fmaf(z[s  ].y,y0.y, fmaf(z[s  ].z,y0.z, fmaf(z[s  ].w,y0.w, a0))));
            a1 = fmaf(z[s+1].x,y1.x, fmaf(z[s+1].y,y1.y, fmaf(z[s+1].z,y1.z, fmaf(z[s+1].w,y1.w, a1))));
            a2 = fmaf(z[s+2].x,y2.x, fmaf(z[s+2].y,y2.y, fmaf(z[s+2].z,y2.z, fmaf(z[s+2].w,y2.w, a2))));
            a3 = fmaf(z[s+3].x,y3.x, fmaf(z[s+3].y,y3.y, fmaf(z[s+3].z,y3.z, fmaf(z[s+3].w,y3.w, a3))));
        }
        c[j] = (a0 + a1) + (a2 + a3);
    }

    // Stage 2 fused with RoPE, write back to own row (exclusive, no race)
    float* myRowW = (float*)((char*)sBuf + tid * (DD * 4));
    #pragma unroll
    for (int s = 0; s < 16; s++) {
        int col = (tid + s) & 15;
        float4 acc = z[s];
        #pragma unroll
        for (int j = 0; j < MM; j++) {
            float4 w = *(const float4*)((const char*)sW + j * (DD * 4) + col * 16);
            float cj = c[j];
            acc.x = fmaf(cj, w.x, acc.x);
            acc.y = fmaf(cj, w.y, acc.y);
            acc.z = fmaf(cj, w.z, acc.z);
            acc.w = fmaf(cj, w.w, acc.w);
        }
        float4 o4;
        #pragma unroll
        for (int half = 0; half < 2; half++) {
            int p = 2*col + half;
            float xe = half ? acc.z : acc.x;
            float xo = half ? acc.w : acc.y;
            float a = tf * sFreq[p];                 // matches reference f32 product
            float n = rintf(a * INV2PI);
            float r = fmaf(-n, RC1, a);
            r = fmaf(-n, RC2, r);
            r = fmaf(-n, RC3, r);                    // |r| <= pi, ~4e-7 abs err
            float sv = __sinf(r);
            float cv = __cosf(r);
            float re = fmaf(-xo, sv, xe * cv);
            float ro = fmaf( xo, cv, xe * sv);
            if (half == 0) { o4.x = re; o4.y = ro; }
            else           { o4.z = re; o4.w = ro; }
        }
        *(float4*)((char*)myRowW + col * 16) = o4;
    }
    __syncthreads();

    // Bulk store SMEM -> GMEM
    if (tid == 0) {
        asm volatile("fence.proxy.async.shared::cta;" ::: "memory");
        float* dst = out + (size_t)bid * (VPB * DD);
        asm volatile("cp.async.bulk.global.shared::cta.bulk_group [%0], [%1], %2;"
                     :: "l"(dst), "r"(bufA), "r"((uint32_t)TILE_BYTES) : "memory");
        asm volatile("cp.async.bulk.commit_group;" ::: "memory");
        asm volatile("cp.async.bulk.wait_group 0;" ::: "memory");
    }
}

// ---------------------------------------------------------------------------
extern "C" void kernel_launch(void* const* d_in, const int* in_sizes, int n_in,
                              void* d_out, int out_size) {
    const float* q    = (const float*)d_in[0];
    const float* k    = (const float*)d_in[1];
    const float* V    = (const float*)d_in[2];
    const float* pos  = (const float*)d_in[3];
    const float* freq = (const float*)d_in[4];
    float* out = (float*)d_out;

    prep_wy_kernel<<<HH, 32>>>(V);
    hh_rope_kernel<<<2 * BLOCKS_PER_TENSOR, VPB>>>(q, k, pos, freq, out);
}